// round 15
// baseline (speedup 1.0000x reference)
#include <cuda_runtime.h>
#include <cuda_fp16.h>
#include <math.h>

#define N_NODES 20000
#define N_EDGES 320000
#define G_      64
#define RMAX    5.0f
#define TAB     512
#define NBLK    444         // 148 SMs x 3 blocks resident (<=84 regs)
#define NTHR    256
#define NWARPS  (NBLK * 8)  // 3552
#define NSCB    79          // ceil(20000/256)

// ---------------- device scratch (static; no allocation) ----------------
__device__ float4 g_pos4[N_NODES];
__device__ float  g_attrs[N_NODES * 10];
__device__ float  g_scalar[N_NODES * 32];
__device__ float  g_pred[N_NODES * 13];
__device__ float4 g_vt[N_EDGES];            // (ux,uy,uz,tc); tc>=TAB-1 => inactive
__device__ int    g_deg[N_NODES];
__device__ int    g_rowptr[N_NODES + 1];
__device__ int    g_cursor[N_NODES];
__device__ int    g_part[NSCB];
__device__ int    g_wstart[NWARPS + 1];
__device__ int4   c_e[N_EDGES];             // {sender, h2(ux,uy), h2(uz,0), f32 tc}
__device__ float  g_rwtab[2 * TAB * 64];
__device__ __half2 g_tabh[2 * TAB * 64];
__device__ float  g_lacc[G_];
__device__ int    g_lcnt[G_];

// ---------------- grid barrier (all blocks resident) ----------------
__device__ unsigned g_barArr = 0;
__device__ unsigned g_barGen = 0;

__device__ __forceinline__ void gridbar() {
    __syncthreads();
    if (threadIdx.x == 0) {
        __threadfence();
        unsigned gen = *(volatile unsigned*)&g_barGen;
        unsigned old = atomicAdd(&g_barArr, 1u);
        if (old == NBLK - 1) {
            g_barArr = 0;
            __threadfence();
            atomicAdd(&g_barGen, 1u);
        } else {
            while (*(volatile unsigned*)&g_barGen == gen) __nanosleep(64);
        }
        __threadfence();
    }
    __syncthreads();
}

// ---------------- per-edge accumulate ----------------
__device__ __forceinline__ void edge_acc(int4 rec, float sc, float2 tv,
                                         float& a0, float& a1, float& a2, float& a3) {
    float tc = __int_as_float(rec.w);
    int i0 = (int)tc;
    float fr = tc - (float)i0;
    const __half2* hp = (const __half2*)&tv;
    float2 q0 = __half22float2(hp[0]);
    float2 q1 = __half22float2(hp[1]);
    float2 uxy = __half22float2(*(const __half2*)&rec.y);
    float uz = __low2float(*(const __half2*)&rec.z);
    float m0 = sc * fmaf(fr, q0.y, q0.x);
    float m1 = sc * fmaf(fr, q1.y, q1.x);
    a0 += m0;
    a1 = fmaf(m1, uxy.x, a1);
    a2 = fmaf(m1, uxy.y, a2);
    a3 = fmaf(m1, uz,    a3);
}

// ---------------- fused layer phase ----------------
template <int LAYER>
__device__ __forceinline__ void layer_phase(float* Wint, float4* stage,
                                            const float* __restrict__ W_mix,
                                            const float* __restrict__ W_prod,
                                            const float* __restrict__ W_sc,
                                            const float* __restrict__ W_ro_s,
                                            const float* __restrict__ W_ro_v,
                                            const float* __restrict__ eps,
                                            const int* __restrict__ batch) {
    // interleaved W_mix: Wint[c*64 + d*2 + which]
    for (int i = threadIdx.x; i < 2048; i += NTHR) {
        int c = i >> 6, r = i & 63, d = r >> 1, which = r & 1;
        Wint[i] = W_mix[LAYER * 4096 + which * 1024 + c * 32 + d];
    }
    __syncthreads();

    int warp = threadIdx.x >> 5, lane = threadIdx.x & 31;
    int w = blockIdx.x * 8 + warp;
    int ns = g_wstart[w], ne = g_wstart[w + 1];
    const float2* tab = (const float2*)(g_tabh + LAYER * TAB * 64);
    float4* mystage = stage + warp * 32;
    float* stage_f = (float*)mystage;

    float wpa = __ldg(&W_prod[LAYER * 96 + lane]);
    float wpb = __ldg(&W_prod[LAYER * 96 + 32 + lane]);
    float wpc = __ldg(&W_prod[LAYER * 96 + 64 + lane]);

    for (int n = ns; n < ne; n++) {
        float a0 = 0.0f, a1 = 0.0f, a2 = 0.0f, a3 = 0.0f;
        int beg = g_rowptr[n], end = g_rowptr[n + 1];
        int p = beg;
        // 8-wide batched loads: deep MLP on the random gathers
        for (; p + 8 <= end; p += 8) {
            int4 r0 = __ldg(&c_e[p + 0]);
            int4 r1 = __ldg(&c_e[p + 1]);
            int4 r2 = __ldg(&c_e[p + 2]);
            int4 r3 = __ldg(&c_e[p + 3]);
            int4 r4 = __ldg(&c_e[p + 4]);
            int4 r5 = __ldg(&c_e[p + 5]);
            int4 r6 = __ldg(&c_e[p + 6]);
            int4 r7 = __ldg(&c_e[p + 7]);
            float s0 = __ldg(&g_scalar[r0.x * 32 + lane]);
            float s1 = __ldg(&g_scalar[r1.x * 32 + lane]);
            float s2 = __ldg(&g_scalar[r2.x * 32 + lane]);
            float s3 = __ldg(&g_scalar[r3.x * 32 + lane]);
            float s4 = __ldg(&g_scalar[r4.x * 32 + lane]);
            float s5 = __ldg(&g_scalar[r5.x * 32 + lane]);
            float s6 = __ldg(&g_scalar[r6.x * 32 + lane]);
            float s7 = __ldg(&g_scalar[r7.x * 32 + lane]);
            float2 t0 = __ldg(tab + ((int)__int_as_float(r0.w)) * 32 + lane);
            float2 t1 = __ldg(tab + ((int)__int_as_float(r1.w)) * 32 + lane);
            float2 t2 = __ldg(tab + ((int)__int_as_float(r2.w)) * 32 + lane);
            float2 t3 = __ldg(tab + ((int)__int_as_float(r3.w)) * 32 + lane);
            float2 t4 = __ldg(tab + ((int)__int_as_float(r4.w)) * 32 + lane);
            float2 t5 = __ldg(tab + ((int)__int_as_float(r5.w)) * 32 + lane);
            float2 t6 = __ldg(tab + ((int)__int_as_float(r6.w)) * 32 + lane);
            float2 t7 = __ldg(tab + ((int)__int_as_float(r7.w)) * 32 + lane);
            edge_acc(r0, s0, t0, a0, a1, a2, a3);
            edge_acc(r1, s1, t1, a0, a1, a2, a3);
            edge_acc(r2, s2, t2, a0, a1, a2, a3);
            edge_acc(r3, s3, t3, a0, a1, a2, a3);
            edge_acc(r4, s4, t4, a0, a1, a2, a3);
            edge_acc(r5, s5, t5, a0, a1, a2, a3);
            edge_acc(r6, s6, t6, a0, a1, a2, a3);
            edge_acc(r7, s7, t7, a0, a1, a2, a3);
        }
        for (; p + 4 <= end; p += 4) {
            int4 r0 = __ldg(&c_e[p + 0]);
            int4 r1 = __ldg(&c_e[p + 1]);
            int4 r2 = __ldg(&c_e[p + 2]);
            int4 r3 = __ldg(&c_e[p + 3]);
            float s0 = __ldg(&g_scalar[r0.x * 32 + lane]);
            float s1 = __ldg(&g_scalar[r1.x * 32 + lane]);
            float s2 = __ldg(&g_scalar[r2.x * 32 + lane]);
            float s3 = __ldg(&g_scalar[r3.x * 32 + lane]);
            float2 t0 = __ldg(tab + ((int)__int_as_float(r0.w)) * 32 + lane);
            float2 t1 = __ldg(tab + ((int)__int_as_float(r1.w)) * 32 + lane);
            float2 t2 = __ldg(tab + ((int)__int_as_float(r2.w)) * 32 + lane);
            float2 t3 = __ldg(tab + ((int)__int_as_float(r3.w)) * 32 + lane);
            edge_acc(r0, s0, t0, a0, a1, a2, a3);
            edge_acc(r1, s1, t1, a0, a1, a2, a3);
            edge_acc(r2, s2, t2, a0, a1, a2, a3);
            edge_acc(r3, s3, t3, a0, a1, a2, a3);
        }
        for (; p < end; p++) {
            int4 r0 = __ldg(&c_e[p]);
            float s0 = __ldg(&g_scalar[r0.x * 32 + lane]);
            float2 t0 = __ldg(tab + ((int)__int_as_float(r0.w)) * 32 + lane);
            edge_acc(r0, s0, t0, a0, a1, a2, a3);
        }

        // stage accumulators, mix via broadcast LDS
        mystage[lane] = make_float4(a0, a1, a2, a3);
        __syncwarp();
        float f0 = 0.0f, f1 = 0.0f, f2 = 0.0f, f3 = 0.0f;
#pragma unroll
        for (int c = 0; c < 32; c++) {
            float4 av = mystage[c];
            float2 wv = *(const float2*)&Wint[c * 64 + lane * 2];
            f0 = fmaf(av.x, wv.x, f0);
            f1 = fmaf(av.y, wv.y, f1);
            f2 = fmaf(av.z, wv.y, f2);
            f3 = fmaf(av.w, wv.y, f3);
        }

        float s0 = f0;
        float p2 = fmaf(fmaf(wpc, s0, wpb), s0, wpa);
        f0 *= p2; f1 *= p2; f2 *= p2; f3 *= p2;

        if (LAYER == 0) {
            float scv = 0.0f;
#pragma unroll
            for (int i = 0; i < 10; i++)
                scv = fmaf(g_attrs[n * 10 + i], __ldg(&W_sc[i * 32 + lane]), scv);
            f0 += scv;
        }
        g_scalar[n * 32 + lane] = f0;

        __syncwarp();
        mystage[lane] = make_float4(f0, f1, f2, f3);
        __syncwarp();

        float e2 = 0.0f;
        if (lane < 13) {
            bool isv = lane >= 10;
            const float* wp = isv ? (W_ro_v + LAYER * 32)
                                  : (W_ro_s + LAYER * 320 + lane);
            int stride = isv ? 1 : 10;
            int comp = isv ? (lane - 9) : 0;
            float acc = 0.0f;
#pragma unroll 8
            for (int c = 0; c < 32; c++)
                acc = fmaf(stage_f[(c << 2) + comp], __ldg(wp + c * stride), acc);
            if (LAYER == 0) {
                g_pred[n * 13 + lane] = acc;
            } else {
                float d = g_pred[n * 13 + lane] + acc - eps[n * 13 + lane];
                e2 = d * d;
            }
        }
        if (LAYER == 1) {
#pragma unroll
            for (int o = 8; o; o >>= 1) e2 += __shfl_xor_sync(0xffffffffu, e2, o);
            if (lane == 0) {
                int g = batch[n];
                atomicAdd(&g_lacc[g], e2);
                atomicAdd(&g_lcnt[g], 1);
            }
        }
        __syncwarp();
    }
}

// ---------------- the mega-kernel ----------------
__global__ void __launch_bounds__(NTHR, 3)
k_mega(const float* __restrict__ pos,
       const float* __restrict__ attrs,
       const float* __restrict__ shifts,
       const float* __restrict__ eps,
       const float* __restrict__ alpha_bar,
       const float* __restrict__ W_embed,
       const float* __restrict__ W_r1,
       const float* __restrict__ W_r2,
       const float* __restrict__ W_mix,
       const float* __restrict__ W_sc,
       const float* __restrict__ W_prod,
       const float* __restrict__ W_ro_s,
       const float* __restrict__ W_ro_v,
       const int* __restrict__ ei,
       const int* __restrict__ batch,
       const int* __restrict__ t,
       float* __restrict__ out) {
    __shared__ float smu[2048];        // union: table hid+sincos / scan / Wint
    __shared__ float4 stage[8 * 32];   // per-warp staging (layer phases)
    int tid = threadIdx.x;
    int bid = blockIdx.x;
    int gtid = bid * NTHR + tid;

    // ======== P0: node init + fp32 radial table ========
    if (gtid < N_NODES) {
        int n = gtid;
        if (n < G_) { g_lacc[n] = 0.0f; g_lcnt[n] = 0; }
        g_deg[n] = 0;
        int b = batch[n];
        int tt = t[b];
        float ab = alpha_bar[tt];
        float sa = sqrtf(ab), sb = sqrtf(1.0f - ab);
        g_pos4[n] = make_float4(sa * pos[n * 3 + 0] + sb * eps[n * 13 + 10],
                                sa * pos[n * 3 + 1] + sb * eps[n * 13 + 11],
                                sa * pos[n * 3 + 2] + sb * eps[n * 13 + 12], 0.0f);
        float an[10];
#pragma unroll
        for (int i = 0; i < 10; i++) {
            an[i] = sa * attrs[n * 10 + i] * 0.25f + sb * eps[n * 13 + i];
            g_attrs[n * 10 + i] = an[i];
        }
        float tf = (float)tt / 1000.0f;
#pragma unroll 4
        for (int c = 0; c < 32; c++) {
            float h = tf * W_embed[10 * 32 + c];
#pragma unroll
            for (int i = 0; i < 10; i++) h += an[i] * W_embed[i * 32 + c];
            g_scalar[n * 32 + c] = h;
        }
    }
    // radial table: 4 rows per block; sin(n*th) via Chebyshev recurrence
    {
        int sub = tid >> 6;
        int j = tid & 63;
        for (int chunk = bid; chunk < (2 * TAB) / 4; chunk += NBLK) {
            __syncthreads();
            int row = chunk * 4 + sub;
            int l = row / TAB;
            int i = row & (TAB - 1);
            float r = (float)i * (RMAX / (float)(TAB - 1));
            float rc = fmaxf(r, 1e-9f);
            if (j == 0) {
                const float PI_ = 3.14159265358979323846f;
                float th = PI_ * rc / RMAX;
                smu[1024 + sub * 2 + 0] = sinf(th);
                smu[1024 + sub * 2 + 1] = cosf(th);
            }
            __syncthreads();
            float s1 = smu[1024 + sub * 2 + 0];
            float c2 = 2.0f * smu[1024 + sub * 2 + 1];
            float xr = r / RMAX;
            float xr2 = xr * xr;
            float xr6 = xr2 * xr2 * xr2;
            float f = 1.0f - 28.0f * xr6 + 48.0f * xr6 * xr - 21.0f * xr6 * xr2;
            if (xr >= 1.0f) f = 0.0f;
            float g = 0.6324555320336759f * f / rc;
            float sp = 0.0f, sn = s1;
            float h = 0.0f;
#pragma unroll
            for (int nb = 0; nb < 8; nb++) {
                h = fmaf(g * sn, W_r1[l * 512 + nb * 64 + j], h);
                float nx = fmaf(c2, sn, -sp);
                sp = sn; sn = nx;
            }
            smu[sub * 64 + j] = h / (1.0f + __expf(-h));
            __syncthreads();
            int col = ((j >> 1) << 2) | (j & 1);
            float acc = 0.0f;
#pragma unroll 8
            for (int h0 = 0; h0 < 64; h0++)
                acc += smu[sub * 64 + h0] * W_r2[l * 8192 + h0 * 128 + col];
            g_rwtab[row * 64 + j] = acc;
        }
    }
    gridbar();

    // ======== P1: edge geometry (store g_vt) + degree ========
    for (int e = gtid; e < N_EDGES; e += NBLK * NTHR) {
        int s = ei[e], rc = ei[N_EDGES + e];
        float4 pr = __ldg(&g_pos4[rc]);
        float4 ps = __ldg(&g_pos4[s]);
        float vx = pr.x - ps.x + shifts[e * 3 + 0];
        float vy = pr.y - ps.y + shifts[e * 3 + 1];
        float vz = pr.z - ps.z + shifts[e * 3 + 2];
        float r = sqrtf(vx * vx + vy * vy + vz * vz + 1e-12f);
        float inv = 1.0f / r;
        float tc = r * ((float)(TAB - 1) / RMAX);   // >= TAB-1 iff r >= RMAX
        g_vt[e] = make_float4(vx * inv, vy * inv, vz * inv, tc);
        if (r < RMAX) atomicAdd(&g_deg[rc], 1);
    }
    gridbar();

    // ======== P2: scan partials (blocks < NSCB) || table pack (rest) ========
    if (bid < NSCB) {
        int* shi = (int*)smu;
        int i = bid * 256 + tid;
        shi[tid] = (i < N_NODES) ? g_deg[i] : 0;
        __syncthreads();
        for (int off = 128; off; off >>= 1) {
            if (tid < off) shi[tid] += shi[tid + off];
            __syncthreads();
        }
        if (tid == 0) g_part[bid] = shi[0];
    } else {
        int base = (bid - NSCB) * NTHR + tid;
        for (int idx = base; idx < 2 * TAB * 64; idx += (NBLK - NSCB) * NTHR) {
            int row = idx >> 6;
            int il = row & (TAB - 1);
            int j = idx & 63;
            float scale = (j & 1) ? 0.10825317547305482f : 0.0625f;  // sqrt3/16 : 1/16
            float a = g_rwtab[idx] * scale;
            float d = (il < TAB - 1) ? (g_rwtab[idx + 64] * scale - a) : 0.0f;
            g_tabh[idx] = __floats2half2_rn(a, d);
        }
    }
    gridbar();

    // ======== P3: per-chunk offsets + local scan (blocks < NSCB) ========
    if (bid < NSCB) {
        int* shi = (int*)smu;
        int lane = tid & 31;
        int v = (tid < NSCB) ? g_part[tid] : 0;
        int below = (tid < bid) ? v : 0;
#pragma unroll
        for (int o = 16; o; o >>= 1) below += __shfl_xor_sync(0xffffffffu, below, o);
        __shared__ int s_off[8], s_tot[8];
        int w = tid >> 5;
        if (lane == 0) s_off[w] = below;
        int totp = v;
#pragma unroll
        for (int o = 16; o; o >>= 1) totp += __shfl_xor_sync(0xffffffffu, totp, o);
        if (lane == 0) s_tot[w] = totp;
        __syncthreads();
        int blkoff = 0, total = 0;
#pragma unroll
        for (int q = 0; q < 8; q++) { blkoff += s_off[q]; total += s_tot[q]; }
        int i = bid * 256 + tid;
        int dv = (i < N_NODES) ? g_deg[i] : 0;
        shi[tid] = dv;
        __syncthreads();
        for (int off = 1; off < 256; off <<= 1) {
            int u = (tid >= off) ? shi[tid - off] : 0;
            __syncthreads();
            shi[tid] += u;
            __syncthreads();
        }
        if (i < N_NODES) {
            int excl = shi[tid] - dv + blkoff;
            g_rowptr[i] = excl;
            g_cursor[i] = excl;
        }
        if (bid == NSCB - 1 && tid == 0) g_rowptr[N_NODES] = total;
    }
    gridbar();

    // ======== P4: balanced warp partition + CSR fill ========
    if (gtid <= NWARPS) {
        int tot = g_rowptr[N_NODES];
        int F = tot + 16 * N_NODES;
        int target = (int)(((long long)gtid * F) / NWARPS);
        int lo = 0, hi = N_NODES;
        while (lo < hi) {
            int mid = (lo + hi) >> 1;
            int key = g_rowptr[mid] + 16 * mid;
            if (key >= target) hi = mid; else lo = mid + 1;
        }
        g_wstart[gtid] = lo;
    }
    for (int e = gtid; e < N_EDGES; e += NBLK * NTHR) {
        float4 v = g_vt[e];
        if (v.w >= (float)(TAB - 1)) continue;
        int rc = ei[N_EDGES + e];
        int p = atomicAdd(&g_cursor[rc], 1);
        __half2 hxy = __floats2half2_rn(v.x, v.y);
        __half2 hz  = __floats2half2_rn(v.z, 0.0f);
        int4 rec;
        rec.x = ei[e];
        rec.y = *(const int*)&hxy;
        rec.z = *(const int*)&hz;
        rec.w = __float_as_int(v.w);
        c_e[p] = rec;
    }
    gridbar();

    // ======== P5/P6: layers ========
    layer_phase<0>(smu, stage, W_mix, W_prod, W_sc, W_ro_s, W_ro_v, eps, batch);
    gridbar();
    layer_phase<1>(smu, stage, W_mix, W_prod, W_sc, W_ro_s, W_ro_v, eps, batch);
    gridbar();

    // ======== P7: final output ========
    if (bid == 0 && tid < G_) {
        float nn = fmaxf((float)g_lcnt[tid], 1.0f);
        out[tid] = 0.5f * g_lacc[tid] / (nn * 13.0f);
    }
}

// ---------------- launcher ----------------
extern "C" void kernel_launch(void* const* d_in, const int* in_sizes, int n_in,
                              void* d_out, int out_size) {
    (void)in_sizes; (void)n_in; (void)out_size;
    k_mega<<<NBLK, NTHR>>>(
        (const float*)d_in[0],  (const float*)d_in[1],  (const float*)d_in[2],
        (const float*)d_in[3],  (const float*)d_in[4],  (const float*)d_in[5],
        (const float*)d_in[6],  (const float*)d_in[7],  (const float*)d_in[8],
        (const float*)d_in[9],  (const float*)d_in[10], (const float*)d_in[11],
        (const float*)d_in[12], (const int*)d_in[13],   (const int*)d_in[14],
        (const int*)d_in[15],   (float*)d_out);
}

// round 16
// speedup vs baseline: 1.6711x; 1.6711x over previous
#include <cuda_runtime.h>
#include <cuda_fp16.h>
#include <math.h>

#define N_NODES 20000
#define N_EDGES 320000
#define G_      64
#define RMAX    5.0f
#define TAB     512
#define NBLK    592         // 148 SMs x 4 blocks resident (64 regs)
#define NTHR    256
#define NWARPS  (NBLK * 8)  // 4736
#define NSCB    79          // ceil(20000/256)

// ---------------- device scratch (static; no allocation) ----------------
__device__ float4 g_pos4[N_NODES];
__device__ float  g_attrs[N_NODES * 10];
__device__ float  g_scalar2[N_NODES * 64];  // premixed sender scalars (sc0', sc1') interleaved
__device__ float  g_pred[N_NODES * 13];
__device__ int4   g_ve[N_EDGES];            // full edge record; tc>=TAB-1 => inactive
__device__ int    g_deg[N_NODES];
__device__ int    g_rowptr[N_NODES + 1];
__device__ int    g_cursor[N_NODES];
__device__ int    g_part[NSCB];
__device__ int    g_wstart[NWARPS + 1];
__device__ int4   c_e[N_EDGES];             // {sender, h2(ux,uy), h2(uz)|rc<<16, f32 tc}
__device__ float  g_rwtab[2 * TAB * 64];
__device__ __half2 g_tabh[2 * TAB * 64];
__device__ float  g_lacc[G_];
__device__ int    g_lcnt[G_];

// ---------------- grid barrier (all blocks resident) ----------------
__device__ unsigned g_barArr = 0;
__device__ unsigned g_barGen = 0;

__device__ __forceinline__ void gridbar() {
    __syncthreads();
    if (threadIdx.x == 0) {
        __threadfence();
        unsigned gen = *(volatile unsigned*)&g_barGen;
        unsigned old = atomicAdd(&g_barArr, 1u);
        if (old == NBLK - 1) {
            g_barArr = 0;
            __threadfence();
            atomicAdd(&g_barGen, 1u);
        } else {
            while (*(volatile unsigned*)&g_barGen == gen) __nanosleep(64);
        }
        __threadfence();
    }
    __syncthreads();
}

// ---------------- per-edge accumulate (premixed scalars) ----------------
__device__ __forceinline__ void edge_acc(int4 rec, float2 sc, float2 tv,
                                         float& a0, float& a1, float& a2, float& a3) {
    float tc = __int_as_float(rec.w);
    int i0 = (int)tc;
    float fr = tc - (float)i0;
    const __half2* hp = (const __half2*)&tv;
    float2 q0 = __half22float2(hp[0]);
    float2 q1 = __half22float2(hp[1]);
    float2 uxy = __half22float2(*(const __half2*)&rec.y);
    float uz = __low2float(*(const __half2*)&rec.z);
    float m0 = sc.x * fmaf(fr, q0.y, q0.x);
    float m1 = sc.y * fmaf(fr, q1.y, q1.x);
    a0 += m0;
    a1 = fmaf(m1, uxy.x, a1);
    a2 = fmaf(m1, uxy.y, a2);
    a3 = fmaf(m1, uz,    a3);
}

// ---------------- fused layer phase (accumulators ARE feats) ----------------
template <int LAYER>
__device__ __forceinline__ void layer_phase(float* Wint, float4* stage,
                                            const float* __restrict__ W_mix,
                                            const float* __restrict__ W_prod,
                                            const float* __restrict__ W_sc,
                                            const float* __restrict__ W_ro_s,
                                            const float* __restrict__ W_ro_v,
                                            const float* __restrict__ eps,
                                            const int* __restrict__ batch) {
    if (LAYER == 0) {
        // epilogue of layer 0 premixes NEXT layer's scalars: load W_mix[1]
        for (int i = threadIdx.x; i < 2048; i += NTHR) {
            int c = i >> 6, r = i & 63, d = r >> 1, which = r & 1;
            Wint[i] = W_mix[4096 + which * 1024 + c * 32 + d];
        }
        __syncthreads();
    }

    int warp = threadIdx.x >> 5, lane = threadIdx.x & 31;
    int w = blockIdx.x * 8 + warp;
    int ns = g_wstart[w], ne = g_wstart[w + 1];
    const float2* tab = (const float2*)(g_tabh + LAYER * TAB * 64);
    const float2* sc2 = (const float2*)g_scalar2;
    float4* mystage = stage + warp * 32;
    float* stage_f = (float*)mystage;

    float wpa = __ldg(&W_prod[LAYER * 96 + lane]);
    float wpb = __ldg(&W_prod[LAYER * 96 + 32 + lane]);
    float wpc = __ldg(&W_prod[LAYER * 96 + 64 + lane]);

    for (int n = ns; n < ne; n++) {
        float a0 = 0.0f, a1 = 0.0f, a2 = 0.0f, a3 = 0.0f;
        int beg = g_rowptr[n], end = g_rowptr[n + 1];
        int p = beg;
        // 4-wide batched loads: MLP ~4 on the random gathers
        for (; p + 4 <= end; p += 4) {
            int4 r0 = __ldg(&c_e[p + 0]);
            int4 r1 = __ldg(&c_e[p + 1]);
            int4 r2 = __ldg(&c_e[p + 2]);
            int4 r3 = __ldg(&c_e[p + 3]);
            float2 s0 = __ldg(&sc2[r0.x * 32 + lane]);
            float2 s1 = __ldg(&sc2[r1.x * 32 + lane]);
            float2 s2 = __ldg(&sc2[r2.x * 32 + lane]);
            float2 s3 = __ldg(&sc2[r3.x * 32 + lane]);
            float2 t0 = __ldg(tab + ((int)__int_as_float(r0.w)) * 32 + lane);
            float2 t1 = __ldg(tab + ((int)__int_as_float(r1.w)) * 32 + lane);
            float2 t2 = __ldg(tab + ((int)__int_as_float(r2.w)) * 32 + lane);
            float2 t3 = __ldg(tab + ((int)__int_as_float(r3.w)) * 32 + lane);
            edge_acc(r0, s0, t0, a0, a1, a2, a3);
            edge_acc(r1, s1, t1, a0, a1, a2, a3);
            edge_acc(r2, s2, t2, a0, a1, a2, a3);
            edge_acc(r3, s3, t3, a0, a1, a2, a3);
        }
        for (; p < end; p++) {
            int4 r0 = __ldg(&c_e[p]);
            float2 s0 = __ldg(&sc2[r0.x * 32 + lane]);
            float2 t0 = __ldg(tab + ((int)__int_as_float(r0.w)) * 32 + lane);
            edge_acc(r0, s0, t0, a0, a1, a2, a3);
        }

        // accumulators are already the mixed feats (premixed scalars)
        float f0 = a0, f1 = a1, f2 = a2, f3 = a3;
        float s0v = f0;
        float p2 = fmaf(fmaf(wpc, s0v, wpb), s0v, wpa);
        f0 *= p2; f1 *= p2; f2 *= p2; f3 *= p2;

        if (LAYER == 0) {
            float scv = 0.0f;
#pragma unroll
            for (int i = 0; i < 10; i++)
                scv = fmaf(g_attrs[n * 10 + i], __ldg(&W_sc[i * 32 + lane]), scv);
            f0 += scv;
        }

        mystage[lane] = make_float4(f0, f1, f2, f3);
        __syncwarp();

        float e2 = 0.0f;
        if (lane < 13) {
            bool isv = lane >= 10;
            const float* wp = isv ? (W_ro_v + LAYER * 32)
                                  : (W_ro_s + LAYER * 320 + lane);
            int stride = isv ? 1 : 10;
            int comp = isv ? (lane - 9) : 0;
            float acc = 0.0f;
#pragma unroll 8
            for (int c = 0; c < 32; c++)
                acc = fmaf(stage_f[(c << 2) + comp], __ldg(wp + c * stride), acc);
            if (LAYER == 0) {
                g_pred[n * 13 + lane] = acc;
            } else {
                float d = g_pred[n * 13 + lane] + acc - eps[n * 13 + lane];
                e2 = d * d;
            }
        }
        if (LAYER == 0) {
            // premix new scalar (f0 across channels) with W_mix[1] for layer 1
            float p0 = 0.0f, p1 = 0.0f;
#pragma unroll
            for (int c = 0; c < 32; c++) {
                float fc = stage_f[c << 2];     // broadcast
                float2 wv = *(const float2*)&Wint[c * 64 + lane * 2];
                p0 = fmaf(fc, wv.x, p0);
                p1 = fmaf(fc, wv.y, p1);
            }
            ((float2*)g_scalar2)[n * 32 + lane] = make_float2(p0, p1);
        } else {
#pragma unroll
            for (int o = 8; o; o >>= 1) e2 += __shfl_xor_sync(0xffffffffu, e2, o);
            if (lane == 0) {
                int g = batch[n];
                atomicAdd(&g_lacc[g], e2);
                atomicAdd(&g_lcnt[g], 1);
            }
        }
        __syncwarp();
    }
}

// ---------------- the mega-kernel ----------------
__global__ void __launch_bounds__(NTHR, 4)
k_mega(const float* __restrict__ pos,
       const float* __restrict__ attrs,
       const float* __restrict__ shifts,
       const float* __restrict__ eps,
       const float* __restrict__ alpha_bar,
       const float* __restrict__ W_embed,
       const float* __restrict__ W_r1,
       const float* __restrict__ W_r2,
       const float* __restrict__ W_mix,
       const float* __restrict__ W_sc,
       const float* __restrict__ W_prod,
       const float* __restrict__ W_ro_s,
       const float* __restrict__ W_ro_v,
       const int* __restrict__ ei,
       const int* __restrict__ batch,
       const int* __restrict__ t,
       float* __restrict__ out) {
    __shared__ float smu[2048];        // union: table hid+sincos / scan / Wint
    __shared__ float4 stage[8 * 32];   // per-warp staging; P0: WE combined matrix
    int tid = threadIdx.x;
    int bid = blockIdx.x;
    int gtid = bid * NTHR + tid;

    // ======== P0: node init (embedding premixed via WE = W_embed @ W_mix[0]) + radial table ========
    float* WE = (float*)stage;         // 11 x 64 = 704 floats (2816 B <= 4 KB)
    if (bid * NTHR < N_NODES) {
        for (int idx = tid; idx < 704; idx += NTHR) {
            int i = idx / 64, r = idx - (idx / 64) * 64, d = r >> 1, which = r & 1;
            float acc = 0.0f;
#pragma unroll 8
            for (int c = 0; c < 32; c++)
                acc = fmaf(__ldg(&W_embed[i * 32 + c]),
                           __ldg(&W_mix[which * 1024 + c * 32 + d]), acc);
            WE[idx] = acc;
        }
        __syncthreads();
    }
    if (gtid < N_NODES) {
        int n = gtid;
        if (n < G_) { g_lacc[n] = 0.0f; g_lcnt[n] = 0; }
        g_deg[n] = 0;
        int b = batch[n];
        int tt = t[b];
        float ab = alpha_bar[tt];
        float sa = sqrtf(ab), sb = sqrtf(1.0f - ab);
        g_pos4[n] = make_float4(sa * pos[n * 3 + 0] + sb * eps[n * 13 + 10],
                                sa * pos[n * 3 + 1] + sb * eps[n * 13 + 11],
                                sa * pos[n * 3 + 2] + sb * eps[n * 13 + 12], 0.0f);
        float an[10];
#pragma unroll
        for (int i = 0; i < 10; i++) {
            an[i] = sa * attrs[n * 10 + i] * 0.25f + sb * eps[n * 13 + i];
            g_attrs[n * 10 + i] = an[i];
        }
        float tf = (float)tt / 1000.0f;
        // premixed scalars: 64 outputs, 11 FMA each
        for (int r = 0; r < 64; r += 4) {
            float4 v;
            float* vp = (float*)&v;
#pragma unroll
            for (int q = 0; q < 4; q++) {
                float acc = tf * WE[10 * 64 + r + q];
#pragma unroll
                for (int i = 0; i < 10; i++) acc = fmaf(an[i], WE[i * 64 + r + q], acc);
                vp[q] = acc;
            }
            *(float4*)&g_scalar2[n * 64 + r] = v;
        }
    }
    // radial table: 4 rows per block; sin(n*th) via Chebyshev recurrence
    {
        int sub = tid >> 6;
        int j = tid & 63;
        for (int chunk = bid; chunk < (2 * TAB) / 4; chunk += NBLK) {
            __syncthreads();
            int row = chunk * 4 + sub;
            int l = row / TAB;
            int i = row & (TAB - 1);
            float r = (float)i * (RMAX / (float)(TAB - 1));
            float rc = fmaxf(r, 1e-9f);
            if (j == 0) {
                const float PI_ = 3.14159265358979323846f;
                float th = PI_ * rc / RMAX;
                smu[1024 + sub * 2 + 0] = sinf(th);
                smu[1024 + sub * 2 + 1] = cosf(th);
            }
            __syncthreads();
            float s1 = smu[1024 + sub * 2 + 0];
            float c2 = 2.0f * smu[1024 + sub * 2 + 1];
            float xr = r / RMAX;
            float xr2 = xr * xr;
            float xr6 = xr2 * xr2 * xr2;
            float f = 1.0f - 28.0f * xr6 + 48.0f * xr6 * xr - 21.0f * xr6 * xr2;
            if (xr >= 1.0f) f = 0.0f;
            float g = 0.6324555320336759f * f / rc;
            float sp = 0.0f, sn = s1;
            float h = 0.0f;
#pragma unroll
            for (int nb = 0; nb < 8; nb++) {
                h = fmaf(g * sn, W_r1[l * 512 + nb * 64 + j], h);
                float nx = fmaf(c2, sn, -sp);
                sp = sn; sn = nx;
            }
            smu[sub * 64 + j] = h / (1.0f + __expf(-h));
            __syncthreads();
            int col = ((j >> 1) << 2) | (j & 1);
            float acc = 0.0f;
#pragma unroll 8
            for (int h0 = 0; h0 < 64; h0++)
                acc += smu[sub * 64 + h0] * W_r2[l * 8192 + h0 * 128 + col];
            g_rwtab[row * 64 + j] = acc;
        }
    }
    gridbar();

    // ======== P1: edge geometry -> full packed record + degree ========
    for (int e = gtid; e < N_EDGES; e += NBLK * NTHR) {
        int s = ei[e], rc = ei[N_EDGES + e];
        float4 pr = __ldg(&g_pos4[rc]);
        float4 ps = __ldg(&g_pos4[s]);
        float vx = pr.x - ps.x + shifts[e * 3 + 0];
        float vy = pr.y - ps.y + shifts[e * 3 + 1];
        float vz = pr.z - ps.z + shifts[e * 3 + 2];
        float r = sqrtf(vx * vx + vy * vy + vz * vz + 1e-12f);
        float inv = 1.0f / r;
        float tc = r * ((float)(TAB - 1) / RMAX);   // >= TAB-1 iff r >= RMAX
        __half2 hxy = __floats2half2_rn(vx * inv, vy * inv);
        __half  huz = __float2half_rn(vz * inv);
        int4 rec;
        rec.x = s;
        rec.y = *(const int*)&hxy;
        rec.z = (int)__half_as_ushort(huz) | (rc << 16);
        rec.w = __float_as_int(tc);
        g_ve[e] = rec;
        if (r < RMAX) atomicAdd(&g_deg[rc], 1);
    }
    gridbar();

    // ======== P2: scan partials (blocks < NSCB) || table pack (rest) ========
    if (bid < NSCB) {
        int* shi = (int*)smu;
        int i = bid * 256 + tid;
        shi[tid] = (i < N_NODES) ? g_deg[i] : 0;
        __syncthreads();
        for (int off = 128; off; off >>= 1) {
            if (tid < off) shi[tid] += shi[tid + off];
            __syncthreads();
        }
        if (tid == 0) g_part[bid] = shi[0];
    } else {
        int base = (bid - NSCB) * NTHR + tid;
        for (int idx = base; idx < 2 * TAB * 64; idx += (NBLK - NSCB) * NTHR) {
            int row = idx >> 6;
            int il = row & (TAB - 1);
            int j = idx & 63;
            float scale = (j & 1) ? 0.10825317547305482f : 0.0625f;  // sqrt3/16 : 1/16
            float a = g_rwtab[idx] * scale;
            float d = (il < TAB - 1) ? (g_rwtab[idx + 64] * scale - a) : 0.0f;
            g_tabh[idx] = __floats2half2_rn(a, d);
        }
    }
    gridbar();

    // ======== P3: per-chunk offsets + local scan (blocks < NSCB) ========
    if (bid < NSCB) {
        int* shi = (int*)smu;
        int lane = tid & 31;
        int v = (tid < NSCB) ? g_part[tid] : 0;
        int below = (tid < bid) ? v : 0;
#pragma unroll
        for (int o = 16; o; o >>= 1) below += __shfl_xor_sync(0xffffffffu, below, o);
        __shared__ int s_off[8], s_tot[8];
        int w = tid >> 5;
        if (lane == 0) s_off[w] = below;
        int totp = v;
#pragma unroll
        for (int o = 16; o; o >>= 1) totp += __shfl_xor_sync(0xffffffffu, totp, o);
        if (lane == 0) s_tot[w] = totp;
        __syncthreads();
        int blkoff = 0, total = 0;
#pragma unroll
        for (int q = 0; q < 8; q++) { blkoff += s_off[q]; total += s_tot[q]; }
        int i = bid * 256 + tid;
        int dv = (i < N_NODES) ? g_deg[i] : 0;
        shi[tid] = dv;
        __syncthreads();
        for (int off = 1; off < 256; off <<= 1) {
            int u = (tid >= off) ? shi[tid - off] : 0;
            __syncthreads();
            shi[tid] += u;
            __syncthreads();
        }
        if (i < N_NODES) {
            int excl = shi[tid] - dv + blkoff;
            g_rowptr[i] = excl;
            g_cursor[i] = excl;
        }
        if (bid == NSCB - 1 && tid == 0) g_rowptr[N_NODES] = total;
    }
    gridbar();

    // ======== P4: balanced warp partition + CSR scatter ========
    if (gtid <= NWARPS) {
        int tot = g_rowptr[N_NODES];
        int F = tot + 16 * N_NODES;
        int target = (int)(((long long)gtid * F) / NWARPS);
        int lo = 0, hi = N_NODES;
        while (lo < hi) {
            int mid = (lo + hi) >> 1;
            int key = g_rowptr[mid] + 16 * mid;
            if (key >= target) hi = mid; else lo = mid + 1;
        }
        g_wstart[gtid] = lo;
    }
    for (int e = gtid; e < N_EDGES; e += NBLK * NTHR) {
        int4 rec = __ldg(&g_ve[e]);
        float tc = __int_as_float(rec.w);
        if (tc >= (float)(TAB - 1)) continue;
        int rc = ((unsigned)rec.z) >> 16;
        int p = atomicAdd(&g_cursor[rc], 1);
        c_e[p] = rec;
    }
    gridbar();

    // ======== P5/P6: layers ========
    layer_phase<0>(smu, stage, W_mix, W_prod, W_sc, W_ro_s, W_ro_v, eps, batch);
    gridbar();
    layer_phase<1>(smu, stage, W_mix, W_prod, W_sc, W_ro_s, W_ro_v, eps, batch);
    gridbar();

    // ======== P7: final output ========
    if (bid == 0 && tid < G_) {
        float nn = fmaxf((float)g_lcnt[tid], 1.0f);
        out[tid] = 0.5f * g_lacc[tid] / (nn * 13.0f);
    }
}

// ---------------- launcher ----------------
extern "C" void kernel_launch(void* const* d_in, const int* in_sizes, int n_in,
                              void* d_out, int out_size) {
    (void)in_sizes; (void)n_in; (void)out_size;
    k_mega<<<NBLK, NTHR>>>(
        (const float*)d_in[0],  (const float*)d_in[1],  (const float*)d_in[2],
        (const float*)d_in[3],  (const float*)d_in[4],  (const float*)d_in[5],
        (const float*)d_in[6],  (const float*)d_in[7],  (const float*)d_in[8],
        (const float*)d_in[9],  (const float*)d_in[10], (const float*)d_in[11],
        (const float*)d_in[12], (const int*)d_in[13],   (const int*)d_in[14],
        (const int*)d_in[15],   (float*)d_out);
}